// round 16
// baseline (speedup 1.0000x reference)
#include <cuda_runtime.h>
#include <cuda_bf16.h>
#include <mma.h>
#include <stdint.h>
#include <math.h>

using namespace nvcuda;
typedef unsigned long long ull;
typedef __nv_bfloat16 bf16;

// ---------------- f32x2 packed-math helpers (sm_103a) ----------------
__device__ __forceinline__ ull fma2(ull a, ull b, ull c){
    ull d; asm("fma.rn.f32x2 %0, %1, %2, %3;" : "=l"(d) : "l"(a), "l"(b), "l"(c)); return d;
}
__device__ __forceinline__ ull add2(ull a, ull b){
    ull d; asm("add.rn.f32x2 %0, %1, %2;" : "=l"(d) : "l"(a), "l"(b)); return d;
}
__device__ __forceinline__ ull pack2(float x){
    ull r; asm("mov.b64 %0, {%1, %1};" : "=l"(r) : "f"(x)); return r;
}
__device__ __forceinline__ ull packf2(float a, float b){
    ull r; asm("mov.b64 %0, {%1, %2};" : "=l"(r) : "f"(a), "f"(b)); return r;
}
__device__ __forceinline__ float2 unpack2(ull v){
    float2 r; asm("mov.b64 {%0, %1}, %2;" : "=f"(r.x), "=f"(r.y) : "l"(v)); return r;
}

// ---------------- scratch (device globals; no allocations allowed) ----------------
#define MAXN 50048
#define MAXE 800000

__device__ float g_xl[MAXN * 256];
__device__ float g_xr[MAXN * 256];
__device__ float g_h3[MAXN * 64];
__device__ float g_gvec[64 * 64];
__device__ bf16  g_ah[MAXN * 128];          // node features, bf16 hi (x, then h1, then h2)
__device__ bf16  g_al[MAXN * 128];          // node features, bf16 lo
__device__ bf16  g_wh[3 * 128 * 512];       // weights bf16 hi: [layer][a|b][k][col]
__device__ bf16  g_wl[3 * 128 * 512];       // weights bf16 lo
__device__ int   g_deg[MAXN + 1];
__device__ int   g_rowptr[MAXN + 1];
__device__ int   g_cursor[MAXN];
__device__ int2  g_se[MAXE];

// ---------------- prep: distributed histogram + small single-block scan ------
__global__ void zero_k(int* __restrict__ deg, int n){
    int t = blockIdx.x * blockDim.x + threadIdx.x;
    if (t < n + 1) deg[t] = 0;
}

__global__ void deg_k(const int* __restrict__ dst, int* __restrict__ deg, int E){
    int e = blockIdx.x * blockDim.x + threadIdx.x;
    if (e < E) atomicAdd(&deg[dst[e]], 1);
}

__global__ void scan_k(const int* __restrict__ deg, int* __restrict__ rowptr,
                       int* __restrict__ cursor, int n){
    __shared__ int ss[1024];
    int t = threadIdx.x;
    int chunk = (n + 1023) >> 10;
    int s = t * chunk, e = min(s + chunk, n);
    int a = 0;
    for (int i = s; i < e; i++) a += deg[i];
    ss[t] = a; __syncthreads();
    for (int ofs = 1; ofs < 1024; ofs <<= 1){
        int v = (t >= ofs) ? ss[t - ofs] : 0;
        __syncthreads();
        ss[t] += v;
        __syncthreads();
    }
    int run = (t == 0) ? 0 : ss[t - 1];
    for (int i = s; i < e; i++){ rowptr[i] = run; cursor[i] = run; run += deg[i]; }
    if (t == 1023) rowptr[n] = ss[1023];
}

__global__ void scatter_k(const int* __restrict__ src, const int* __restrict__ dst,
                          int* __restrict__ cursor, int2* __restrict__ se, int E){
    int e = blockIdx.x * blockDim.x + threadIdx.x;
    if (e >= E) return;
    int d = dst[e];
    int slot = atomicAdd(&cursor[d], 1);
    se[slot] = make_int2(src[e], e);
}

// ---------------- f32 -> bf16 hi/lo split conversion (float4 granularity) ----
__global__ void convf_k(const float* __restrict__ s, bf16* __restrict__ h,
                        bf16* __restrict__ l, int n4){
    int t = blockIdx.x * blockDim.x + threadIdx.x;
    if (t >= n4) return;
    float4 v = __ldg((const float4*)s + t);
    bf16 hv[4], lv[4];
    hv[0] = __float2bfloat16(v.x); lv[0] = __float2bfloat16(v.x - __bfloat162float(hv[0]));
    hv[1] = __float2bfloat16(v.y); lv[1] = __float2bfloat16(v.y - __bfloat162float(hv[1]));
    hv[2] = __float2bfloat16(v.z); lv[2] = __float2bfloat16(v.z - __bfloat162float(hv[2]));
    hv[3] = __float2bfloat16(v.w); lv[3] = __float2bfloat16(v.w - __bfloat162float(hv[3]));
    *(ull*)(h + (size_t)t * 4) = *(ull*)hv;
    *(ull*)(l + (size_t)t * 4) = *(ull*)lv;
}

// ---------------- tensor-core dual GEMM (bf16 split, fp32 accumulate) --------
// Y[n,COUT] = X@W + B via 3 bf16 MMA passes (hh, hl, lh). 128 thr = 4 warps;
// warp owns 16 rows x 64 cols. blockIdx.z picks the (Wa,Ya)/(Wb,Yb) problem.
template<int COUT>
__global__ void __launch_bounds__(128) gemm_tc(const bf16* __restrict__ Xh,
                                               const bf16* __restrict__ Xl,
                                               const bf16* __restrict__ Wh,
                                               const bf16* __restrict__ Wl,
                                               const float* __restrict__ Ba,
                                               const float* __restrict__ Bb,
                                               float* __restrict__ Ya,
                                               float* __restrict__ Yb, int n){
    const bf16* WH = Wh + (size_t)blockIdx.z * 128 * COUT;
    const bf16* WL = Wl + (size_t)blockIdx.z * 128 * COUT;
    const float* B = blockIdx.z ? Bb : Ba;
    float*       Y = blockIdx.z ? Yb : Ya;

    int w = threadIdx.x >> 5, lane = threadIdx.x & 31;
    int row0 = blockIdx.y * 64 + w * 16;
    int n0   = blockIdx.x * 64;

    wmma::fragment<wmma::accumulator, 16, 16, 16, float> acc[4];
    #pragma unroll
    for (int j = 0; j < 4; j++) wmma::fill_fragment(acc[j], 0.f);

    #pragma unroll 1
    for (int kc = 0; kc < 8; kc++){
        wmma::fragment<wmma::matrix_a, 16, 16, 16, bf16, wmma::row_major> aH, aL;
        wmma::load_matrix_sync(aH, Xh + (size_t)row0 * 128 + kc * 16, 128);
        wmma::load_matrix_sync(aL, Xl + (size_t)row0 * 128 + kc * 16, 128);
        #pragma unroll
        for (int j = 0; j < 4; j++){
            wmma::fragment<wmma::matrix_b, 16, 16, 16, bf16, wmma::row_major> bH, bL;
            wmma::load_matrix_sync(bH, WH + (size_t)(kc * 16) * COUT + n0 + j * 16, COUT);
            wmma::load_matrix_sync(bL, WL + (size_t)(kc * 16) * COUT + n0 + j * 16, COUT);
            wmma::mma_sync(acc[j], aH, bH, acc[j]);
            wmma::mma_sync(acc[j], aH, bL, acc[j]);
            wmma::mma_sync(acc[j], aL, bH, acc[j]);
        }
    }

    __shared__ float stg[4][16 * 64];
    #pragma unroll
    for (int j = 0; j < 4; j++)
        wmma::store_matrix_sync(&stg[w][j * 16], acc[j], 64, wmma::mem_row_major);
    __syncwarp();

    for (int r2 = 0; r2 < 16; r2 += 2){
        int r = r2 + (lane >> 4);
        int c = (lane & 15) * 4;
        int row = row0 + r;
        if (row < n){
            float4 v = *(float4*)&stg[w][r * 64 + c];
            float4 bv = __ldg((const float4*)(B + n0 + c));
            v.x += bv.x; v.y += bv.y; v.z += bv.z; v.w += bv.w;
            *(float4*)(Y + (size_t)row * COUT + n0 + c) = v;
        }
    }
}

// ---------------- fused GATv2 edge pass (inline ee, 5-edge unroll; R13 body) --
// !MEAN: epilogue emits bf16 hi/lo (feeds next layer's tensor-core GEMM).
// MEAN: f32 atomic head-mean into out (pool applies bias+relu).
template<int CTOT, int LPH, bool MEAN>
__global__ void __launch_bounds__(128, 5) gat_edge(const float* __restrict__ xl,
                                                   const float* __restrict__ xr,
                                                   const float* __restrict__ We,
                                                   const float* __restrict__ att,
                                                   const float* __restrict__ bias,
                                                   const float* __restrict__ eattr,
                                                   const int* __restrict__ rowptr,
                                                   const int2* __restrict__ se,
                                                   float* __restrict__ out,
                                                   bf16* __restrict__ outh,
                                                   bf16* __restrict__ outl, int n){
    constexpr int U = 5;
    const int col0 = blockIdx.y * 128;

    __shared__ float sWe[16 * 128];
    for (int idx = threadIdx.x; idx < 512; idx += 128){
        int k = idx >> 5, c4 = idx & 31;
        ((float4*)sWe)[idx] = __ldg((const float4*)(We + (size_t)k * CTOT + col0 + c4 * 4));
    }
    __syncthreads();

    int warp = threadIdx.x >> 5;
    int lane = threadIdx.x & 31;
    int node = blockIdx.x * 4 + warp;
    if (node >= n) return;

    const float LOG2E = 1.4426950408889634f;
    float4 at4 = __ldg((const float4*)(att + col0 + lane * 4));
    float atv[4] = {at4.x * LOG2E, at4.y * LOG2E, at4.z * LOG2E, at4.w * LOG2E};
    float4 xr4 = __ldg((const float4*)(xr + (size_t)node * CTOT + col0 + lane * 4));
    ull xrv0 = packf2(xr4.x, xr4.y), xrv1 = packf2(xr4.z, xr4.w);

    float l = 0.f;
    ull acc0 = 0ull, acc1 = 0ull;
    ull see0 = 0ull, see1 = 0ull;

    const int start = rowptr[node], endi = rowptr[node + 1];
    const float* wbase = sWe + lane * 4;

    auto FINISH = [&](ull e0, ull e1, float4 xv){
        see0 = add2(see0, e0);
        see1 = add2(see1, e1);
        ull z0 = add2(e0, add2(packf2(xv.x, xv.y), xrv0));
        ull z1 = add2(e1, add2(packf2(xv.z, xv.w), xrv1));
        float2 f0 = unpack2(z0), f1 = unpack2(z1);
        float b0 = fmaxf(f0.x, 0.2f * f0.x);
        float b1 = fmaxf(f0.y, 0.2f * f0.y);
        float b2 = fmaxf(f1.x, 0.2f * f1.x);
        float b3 = fmaxf(f1.y, 0.2f * f1.y);
        float part = b0 * atv[0];
        part = fmaf(b1, atv[1], part);
        part = fmaf(b2, atv[2], part);
        part = fmaf(b3, atv[3], part);
        part += __shfl_xor_sync(0xffffffffu, part, 1);
        part += __shfl_xor_sync(0xffffffffu, part, 2);
        part += __shfl_xor_sync(0xffffffffu, part, 4);
        if (LPH == 16) part += __shfl_xor_sync(0xffffffffu, part, 8);
        float p = exp2f(part);
        l += p;
        ull p2 = pack2(p);
        acc0 = fma2(p2, packf2(xv.x, xv.y), acc0);
        acc1 = fma2(p2, packf2(xv.z, xv.w), acc1);
    };

    int i = start;
    for (; i + U <= endi; i += U){
        int2 pr[U];
        #pragma unroll
        for (int e = 0; e < U; e++) pr[e] = __ldg(se + i + e);
        float4 xv[U];
        #pragma unroll
        for (int e = 0; e < U; e++)
            xv[e] = __ldg((const float4*)(xl + (size_t)pr[e].x * CTOT + col0 + lane * 4));

        ull e0[U], e1[U];
        #pragma unroll
        for (int e = 0; e < U; e++){ e0[e] = 0ull; e1[e] = 0ull; }

        #pragma unroll
        for (int kt = 0; kt < 4; kt++){
            float4 aa[U];
            #pragma unroll
            for (int e = 0; e < U; e++)
                aa[e] = __ldg((const float4*)(eattr + (size_t)pr[e].y * 16 + kt * 4));
            #pragma unroll
            for (int k = 0; k < 4; k++){
                ulonglong2 w = *(const ulonglong2*)(wbase + (kt * 4 + k) * 128);
                #pragma unroll
                for (int e = 0; e < U; e++){
                    float av = (k == 0) ? aa[e].x : (k == 1) ? aa[e].y :
                               (k == 2) ? aa[e].z : aa[e].w;
                    ull a2 = pack2(av);
                    e0[e] = fma2(a2, w.x, e0[e]);
                    e1[e] = fma2(a2, w.y, e1[e]);
                }
            }
        }
        #pragma unroll
        for (int e = 0; e < U; e++) FINISH(e0[e], e1[e], xv[e]);
    }

    for (; i < endi; i++){
        int2 pr = __ldg(se + i);
        float4 xv = __ldg((const float4*)(xl + (size_t)pr.x * CTOT + col0 + lane * 4));
        ull e0 = 0ull, e1 = 0ull;
        #pragma unroll
        for (int kt = 0; kt < 4; kt++){
            float4 aa = __ldg((const float4*)(eattr + (size_t)pr.y * 16 + kt * 4));
            #pragma unroll
            for (int k = 0; k < 4; k++){
                ulonglong2 w = *(const ulonglong2*)(wbase + (kt * 4 + k) * 128);
                float av = (k == 0) ? aa.x : (k == 1) ? aa.y : (k == 2) ? aa.z : aa.w;
                ull a2 = pack2(av);
                e0 = fma2(a2, w.x, e0);
                e1 = fma2(a2, w.y, e1);
            }
        }
        FINISH(e0, e1, xv);
    }

    {   // self loop: ee = mean of incoming edge ee (linearity), xl of self
        ull iv = pack2(1.f / (float)max(endi - start, 1));
        ull e0 = fma2(see0, iv, 0ull);
        ull e1 = fma2(see1, iv, 0ull);
        float4 xv = __ldg((const float4*)(xl + (size_t)node * CTOT + col0 + lane * 4));
        FINISH(e0, e1, xv);
    }

    float inv = 1.f / (l + 1e-16f);
    float2 r0 = unpack2(acc0);
    float2 r1 = unpack2(acc1);
    float o0 = r0.x * inv, o1 = r0.y * inv, o2 = r1.x * inv, o3 = r1.y * inv;

    if (!MEAN){
        float4 bo = __ldg((const float4*)(bias + col0 + lane * 4));
        float v0 = fmaxf(o0 + bo.x, 0.f);
        float v1 = fmaxf(o1 + bo.y, 0.f);
        float v2 = fmaxf(o2 + bo.z, 0.f);
        float v3 = fmaxf(o3 + bo.w, 0.f);
        bf16 hv[4], lv[4];
        hv[0] = __float2bfloat16(v0); lv[0] = __float2bfloat16(v0 - __bfloat162float(hv[0]));
        hv[1] = __float2bfloat16(v1); lv[1] = __float2bfloat16(v1 - __bfloat162float(hv[1]));
        hv[2] = __float2bfloat16(v2); lv[2] = __float2bfloat16(v2 - __bfloat162float(hv[2]));
        hv[3] = __float2bfloat16(v3); lv[3] = __float2bfloat16(v3 - __bfloat162float(hv[3]));
        *(ull*)(outh + (size_t)node * 128 + lane * 4) = *(ull*)hv;
        *(ull*)(outl + (size_t)node * 128 + lane * 4) = *(ull*)lv;
    } else {
        o0 += __shfl_xor_sync(0xffffffffu, o0, 16);
        o1 += __shfl_xor_sync(0xffffffffu, o1, 16);
        o2 += __shfl_xor_sync(0xffffffffu, o2, 16);
        o3 += __shfl_xor_sync(0xffffffffu, o3, 16);
        if (lane < 16){
            float* op = out + (size_t)node * 64 + lane * 4;
            atomicAdd(op + 0, 0.25f * o0);
            atomicAdd(op + 1, 0.25f * o1);
            atomicAdd(op + 2, 0.25f * o2);
            atomicAdd(op + 3, 0.25f * o3);
        }
    }
}

// ---------------- global mean pool (applies layer-3 bias + relu) -------------
__device__ __forceinline__ int lowerb(const int* a, int n, int v){
    int lo = 0, hi = n;
    while (lo < hi){ int md = (lo + hi) >> 1; if (a[md] < v) lo = md + 1; else hi = md; }
    return lo;
}

__global__ void pool_k(const float* __restrict__ h3, const int* __restrict__ batch,
                       const float* __restrict__ bof, float* __restrict__ gvec, int n){
    int g = blockIdx.x;
    int lo = lowerb(batch, n, g), hi = lowerb(batch, n, g + 1);
    int t = threadIdx.x;
    int ch = t & 63, rr = t >> 6;
    float b = __ldg(bof + ch);
    float s = 0.f;
    for (int i = lo + rr; i < hi; i += 4)
        s += fmaxf(h3[(size_t)i * 64 + ch] + b, 0.f);
    __shared__ float red[4][64];
    red[rr][ch] = s; __syncthreads();
    if (rr == 0){
        float tot = red[0][ch] + red[1][ch] + red[2][ch] + red[3][ch];
        float c = (float)max(hi - lo, 1);
        gvec[g * 64 + ch] = tot / c;
    }
}

__global__ void final_k(const float* __restrict__ gvec, const float* __restrict__ Wlin,
                        const float* __restrict__ blin, float* __restrict__ out){
    int t = threadIdx.x;
    int g = t >> 4, o = t & 15;
    float s = 0.f;
    #pragma unroll
    for (int k = 0; k < 64; k++) s = fmaf(gvec[g * 64 + k], Wlin[k * 16 + o], s);
    out[t] = s + blin[o];
}

// ---------------- host orchestration ----------------
extern "C" void kernel_launch(void* const* d_in, const int* in_sizes, int n_in,
                              void* d_out, int out_size){
    const float* x     = (const float*)d_in[0];
    const int*   eidx  = (const int*)  d_in[1];
    const int*   batch = (const int*)  d_in[2];
    const float* eattr = (const float*)d_in[3];
    const float* Wl0 = (const float*)d_in[4],  *bl0 = (const float*)d_in[5];
    const float* Wr0 = (const float*)d_in[6],  *br0 = (const float*)d_in[7];
    const float* We0 = (const float*)d_in[8],  *att0= (const float*)d_in[9];
    const float* bo0 = (const float*)d_in[10];
    const float* Wlh = (const float*)d_in[11], *blh = (const float*)d_in[12];
    const float* Wrh = (const float*)d_in[13], *brh = (const float*)d_in[14];
    const float* Weh = (const float*)d_in[15], *atth= (const float*)d_in[16];
    const float* boh = (const float*)d_in[17];
    const float* Wlf = (const float*)d_in[18], *blf = (const float*)d_in[19];
    const float* Wrf = (const float*)d_in[20], *brf = (const float*)d_in[21];
    const float* Wef = (const float*)d_in[22], *attf= (const float*)d_in[23];
    const float* bof = (const float*)d_in[24];
    const float* Wlin= (const float*)d_in[25], *blin= (const float*)d_in[26];

    int N = in_sizes[0] / 128;
    int E = in_sizes[1] / 2;
    const int* src = eidx;
    const int* dst = eidx + E;

    float *xl, *xr, *h3, *gvec;
    bf16 *ah, *al, *wh, *wl;
    int *deg, *rowptr, *cursor;
    int2 *se;
    cudaGetSymbolAddress((void**)&xl,     g_xl);
    cudaGetSymbolAddress((void**)&xr,     g_xr);
    cudaGetSymbolAddress((void**)&h3,     g_h3);
    cudaGetSymbolAddress((void**)&gvec,   g_gvec);
    cudaGetSymbolAddress((void**)&ah,     g_ah);
    cudaGetSymbolAddress((void**)&al,     g_al);
    cudaGetSymbolAddress((void**)&wh,     g_wh);
    cudaGetSymbolAddress((void**)&wl,     g_wl);
    cudaGetSymbolAddress((void**)&deg,    g_deg);
    cudaGetSymbolAddress((void**)&rowptr, g_rowptr);
    cudaGetSymbolAddress((void**)&cursor, g_cursor);
    cudaGetSymbolAddress((void**)&se,     g_se);

    static cudaStream_t s2 = nullptr;
    static cudaEvent_t evFork = nullptr, evJoin = nullptr;
    if (!s2){
        cudaStreamCreateWithFlags(&s2, cudaStreamNonBlocking);
        cudaEventCreateWithFlags(&evFork, cudaEventDisableTiming);
        cudaEventCreateWithFlags(&evJoin, cudaEventDisableTiming);
    }

    const int LSTR = 128 * 512;                 // per-layer stride in W scratch
    dim3 gT1(2, (N + 63) / 64, 2);              // gemm_tc<128>: 2 col-groups of 64
    dim3 gT2(4, (N + 63) / 64, 2);              // gemm_tc<256>: 4 col-groups of 64
    dim3 ge1((N + 3) / 4, 1), ge2((N + 3) / 4, 2);

    // ---- fork: CSR prep + layer-1/2 weight conversions on s2 ----
    cudaEventRecord(evFork, 0);
    cudaStreamWaitEvent(s2, evFork, 0);

    zero_k   <<<(N + 256) / 256, 256, 0, s2>>>(deg, N);
    deg_k    <<<(E + 255) / 256, 256, 0, s2>>>(dst, deg, E);
    scan_k   <<<1, 1024, 0, s2>>>(deg, rowptr, cursor, N);
    scatter_k<<<(E + 255) / 256, 256, 0, s2>>>(src, dst, cursor, se, E);
    convf_k  <<<(128*128/4 + 255)/256, 256, 0, s2>>>(Wlh, wh + LSTR,            wl + LSTR,            128*128/4);
    convf_k  <<<(128*128/4 + 255)/256, 256, 0, s2>>>(Wrh, wh + LSTR + 128*128,  wl + LSTR + 128*128,  128*128/4);
    convf_k  <<<(128*256/4 + 255)/256, 256, 0, s2>>>(Wlf, wh + 2*LSTR,          wl + 2*LSTR,          128*256/4);
    convf_k  <<<(128*256/4 + 255)/256, 256, 0, s2>>>(Wrf, wh + 2*LSTR + 128*256, wl + 2*LSTR + 128*256, 128*256/4);
    cudaEventRecord(evJoin, s2);

    // ---- main: x + layer-0 W conversion, then gemm0 ----
    cudaMemsetAsync(h3, 0, (size_t)N * 64 * sizeof(float));
    convf_k<<<(N*128/4 + 255)/256, 256>>>(x,   ah, al, N*128/4);
    convf_k<<<(128*128/4 + 255)/256, 256>>>(Wl0, wh,            wl,            128*128/4);
    convf_k<<<(128*128/4 + 255)/256, 256>>>(Wr0, wh + 128*128,  wl + 128*128,  128*128/4);
    gemm_tc<128><<<gT1, 128>>>(ah, al, wh, wl, bl0, br0, xl, xr, N);

    cudaStreamWaitEvent(0, evJoin, 0);   // join: edge pass needs rowptr/se

    // ---- layer 0 edge (writes h1 as bf16 hi/lo into ah/al) ----
    gat_edge<128, 8, false><<<ge1, 128>>>(xl, xr, We0, att0, bo0, eattr,
                                          rowptr, se, nullptr, ah, al, N);
    // ---- layer 1 ----
    gemm_tc<128><<<gT1, 128>>>(ah, al, wh + LSTR, wl + LSTR, blh, brh, xl, xr, N);
    gat_edge<128, 8, false><<<ge1, 128>>>(xl, xr, Weh, atth, boh, eattr,
                                          rowptr, se, nullptr, ah, al, N);
    // ---- layer 2 (head-mean, f32 atomics into h3) ----
    gemm_tc<256><<<gT2, 128>>>(ah, al, wh + 2*LSTR, wl + 2*LSTR, blf, brf, xl, xr, N);
    gat_edge<256, 16, true><<<ge2, 128>>>(xl, xr, Wef, attf, bof, eattr,
                                          rowptr, se, h3, nullptr, nullptr, N);

    pool_k <<<64, 256>>>(h3, batch, bof, gvec, N);
    final_k<<<1, 1024>>>(gvec, Wlin, blin, (float*)d_out);
}

// round 17
// speedup vs baseline: 1.2121x; 1.2121x over previous
#include <cuda_runtime.h>
#include <stdint.h>
#include <math.h>

typedef unsigned long long ull;

// ---------------- f32x2 packed-math helpers (sm_103a) ----------------
__device__ __forceinline__ ull fma2(ull a, ull b, ull c){
    ull d; asm("fma.rn.f32x2 %0, %1, %2, %3;" : "=l"(d) : "l"(a), "l"(b), "l"(c)); return d;
}
__device__ __forceinline__ ull add2(ull a, ull b){
    ull d; asm("add.rn.f32x2 %0, %1, %2;" : "=l"(d) : "l"(a), "l"(b)); return d;
}
__device__ __forceinline__ ull pack2(float x){
    ull r; asm("mov.b64 %0, {%1, %1};" : "=l"(r) : "f"(x)); return r;
}
__device__ __forceinline__ ull packf2(float a, float b){
    ull r; asm("mov.b64 %0, {%1, %2};" : "=l"(r) : "f"(a), "f"(b)); return r;
}
__device__ __forceinline__ float2 unpack2(ull v){
    float2 r; asm("mov.b64 {%0, %1}, %2;" : "=f"(r.x), "=f"(r.y) : "l"(v)); return r;
}
__device__ __forceinline__ float ex2(float x){
    float r; asm("ex2.approx.f32 %0, %1;" : "=f"(r) : "f"(x)); return r;
}
__device__ __forceinline__ void cpasync16(unsigned int saddr, const void* gaddr){
    asm volatile("cp.async.cg.shared.global [%0], [%1], 16;\n" :: "r"(saddr), "l"(gaddr));
}

// ---------------- scratch (device globals; no allocations allowed) ----------------
#define MAXN 50048
#define MAXE 800000

__device__ float g_xl[MAXN * 256];
__device__ float g_xr[MAXN * 256];
__device__ float g_h1[MAXN * 128];
__device__ float g_h2[MAXN * 128];
__device__ float g_h3[MAXN * 64];
__device__ float g_gvec[64 * 64];
__device__ int   g_deg[MAXN + 1];
__device__ int   g_rowptr[MAXN + 1];
__device__ int   g_cursor[MAXN];
__device__ int2  g_se[MAXE];

// ---------------- prep: distributed histogram + small single-block scan ------
__global__ void zero_k(int* __restrict__ deg, int n){
    int t = blockIdx.x * blockDim.x + threadIdx.x;
    if (t < n + 1) deg[t] = 0;
}

__global__ void deg_k(const int* __restrict__ dst, int* __restrict__ deg, int E){
    int e = blockIdx.x * blockDim.x + threadIdx.x;
    if (e < E) atomicAdd(&deg[dst[e]], 1);
}

__global__ void scan_k(const int* __restrict__ deg, int* __restrict__ rowptr,
                       int* __restrict__ cursor, int n){
    __shared__ int ss[1024];
    int t = threadIdx.x;
    int chunk = (n + 1023) >> 10;
    int s = t * chunk, e = min(s + chunk, n);
    int a = 0;
    for (int i = s; i < e; i++) a += deg[i];
    ss[t] = a; __syncthreads();
    for (int ofs = 1; ofs < 1024; ofs <<= 1){
        int v = (t >= ofs) ? ss[t - ofs] : 0;
        __syncthreads();
        ss[t] += v;
        __syncthreads();
    }
    int run = (t == 0) ? 0 : ss[t - 1];
    for (int i = s; i < e; i++){ rowptr[i] = run; cursor[i] = run; run += deg[i]; }
    if (t == 1023) rowptr[n] = ss[1023];
}

__global__ void scatter_k(const int* __restrict__ src, const int* __restrict__ dst,
                          int* __restrict__ cursor, int2* __restrict__ se, int E){
    int e = blockIdx.x * blockDim.x + threadIdx.x;
    if (e >= E) return;
    int d = dst[e];
    int slot = atomicAdd(&cursor[d], 1);
    se[slot] = make_int2(src[e], e);
}

// ---------------- fused dual GEMM (cp.async double-buffered W tiles) ---------
// 128 threads = 4 warps; warp owns 16 rows (TM=16), lane owns 4 cols (TN=4).
// BM=64, BN=128, BK=16. Dynamic smem: sxT (128x68) + sw[2][16x128].
template<int COUT>
__global__ void __launch_bounds__(128) gemm2(const float* __restrict__ X,
                                             const float* __restrict__ Wa,
                                             const float* __restrict__ Ba,
                                             const float* __restrict__ Wb,
                                             const float* __restrict__ Bb,
                                             float* __restrict__ Ya,
                                             float* __restrict__ Yb, int n){
    const float* W = blockIdx.z ? Wb : Wa;
    const float* B = blockIdx.z ? Bb : Ba;
    float*       Y = blockIdx.z ? Yb : Ya;

    extern __shared__ float smem[];
    float* sxT = smem;                 // 128*68
    float* sw  = smem + 128 * 68;      // 2 * 16*128
    int t = threadIdx.x;
    int lane = t & 31, w = t >> 5;
    int row0 = blockIdx.y * 64;
    int cb   = blockIdx.x * 128;

    #pragma unroll
    for (int i = 0; i < 16; i++){
        int f = t + 128 * i;
        int r = f >> 5, c4 = f & 31;
        float4 v = make_float4(0.f, 0.f, 0.f, 0.f);
        if (row0 + r < n) v = __ldg((const float4*)(X + (size_t)(row0 + r) * 128 + c4 * 4));
        sxT[(c4 * 4 + 0) * 68 + r] = v.x;
        sxT[(c4 * 4 + 1) * 68 + r] = v.y;
        sxT[(c4 * 4 + 2) * 68 + r] = v.z;
        sxT[(c4 * 4 + 3) * 68 + r] = v.w;
    }

    auto loadW = [&](int kt, int buf){
        #pragma unroll
        for (int i = 0; i < 4; i++){
            int f = t + 128 * i;
            int k = f >> 5, c4 = f & 31;
            unsigned int sa = (unsigned int)__cvta_generic_to_shared(
                                  &sw[buf * 2048 + k * 128 + c4 * 4]);
            cpasync16(sa, W + (size_t)(kt * 16 + k) * COUT + cb + c4 * 4);
        }
        asm volatile("cp.async.commit_group;\n" ::: "memory");
    };

    ull acc[16][2];
    #pragma unroll
    for (int r = 0; r < 16; r++){ acc[r][0] = 0ull; acc[r][1] = 0ull; }

    loadW(0, 0);

    #pragma unroll 1
    for (int kt = 0; kt < 8; kt++){
        if (kt < 7){
            loadW(kt + 1, (kt + 1) & 1);
            asm volatile("cp.async.wait_group 1;\n" ::: "memory");
        } else {
            asm volatile("cp.async.wait_group 0;\n" ::: "memory");
        }
        __syncthreads();

        const float* swb = sw + (kt & 1) * 2048;
        #pragma unroll
        for (int k = 0; k < 16; k++){
            int kk = kt * 16 + k;
            const float* xb = &sxT[kk * 68 + w * 16];
            float4 x0 = *(const float4*)(xb + 0);
            float4 x1 = *(const float4*)(xb + 4);
            float4 x2 = *(const float4*)(xb + 8);
            float4 x3 = *(const float4*)(xb + 12);
            ulonglong2 wv = *(const ulonglong2*)&swb[k * 128 + lane * 4];
            float xs[16] = {x0.x, x0.y, x0.z, x0.w, x1.x, x1.y, x1.z, x1.w,
                            x2.x, x2.y, x2.z, x2.w, x3.x, x3.y, x3.z, x3.w};
            #pragma unroll
            for (int r = 0; r < 16; r++){
                ull x2r = pack2(xs[r]);
                acc[r][0] = fma2(x2r, wv.x, acc[r][0]);
                acc[r][1] = fma2(x2r, wv.y, acc[r][1]);
            }
        }
        __syncthreads();
    }

    float4 bv = __ldg((const float4*)(B + cb + lane * 4));
    #pragma unroll
    for (int r = 0; r < 16; r++){
        int row = row0 + w * 16 + r;
        if (row < n){
            float2 p0 = unpack2(acc[r][0]);
            float2 p1 = unpack2(acc[r][1]);
            float4 o = make_float4(p0.x + bv.x, p0.y + bv.y, p1.x + bv.z, p1.y + bv.w);
            *(float4*)(Y + (size_t)row * COUT + cb + lane * 4) = o;
        }
    }
}

// ---------------- fused GATv2 edge pass (inline ee, 5-edge unroll; R13 body) --
template<int CTOT, int LPH, bool MEAN>
__global__ void __launch_bounds__(128, 5) gat_edge(const float* __restrict__ xl,
                                                   const float* __restrict__ xr,
                                                   const float* __restrict__ We,
                                                   const float* __restrict__ att,
                                                   const float* __restrict__ bias,
                                                   const float* __restrict__ eattr,
                                                   const int* __restrict__ rowptr,
                                                   const int2* __restrict__ se,
                                                   float* __restrict__ out, int n){
    constexpr int U = 5;
    const int col0 = blockIdx.y * 128;

    __shared__ float sWe[16 * 128];
    for (int idx = threadIdx.x; idx < 512; idx += 128){
        int k = idx >> 5, c4 = idx & 31;
        ((float4*)sWe)[idx] = __ldg((const float4*)(We + (size_t)k * CTOT + col0 + c4 * 4));
    }
    __syncthreads();

    int warp = threadIdx.x >> 5;
    int lane = threadIdx.x & 31;
    int node = blockIdx.x * 4 + warp;
    if (node >= n) return;

    const float LOG2E = 1.4426950408889634f;
    float4 at4 = __ldg((const float4*)(att + col0 + lane * 4));
    float atv[4] = {at4.x * LOG2E, at4.y * LOG2E, at4.z * LOG2E, at4.w * LOG2E};
    float4 xr4 = __ldg((const float4*)(xr + (size_t)node * CTOT + col0 + lane * 4));
    ull xrv0 = packf2(xr4.x, xr4.y), xrv1 = packf2(xr4.z, xr4.w);

    float l = 0.f;
    ull acc0 = 0ull, acc1 = 0ull;
    ull see0 = 0ull, see1 = 0ull;

    const int start = rowptr[node], endi = rowptr[node + 1];
    const float* wbase = sWe + lane * 4;

    auto FINISH = [&](ull e0, ull e1, float4 xv){
        see0 = add2(see0, e0);
        see1 = add2(see1, e1);
        ull z0 = add2(e0, add2(packf2(xv.x, xv.y), xrv0));
        ull z1 = add2(e1, add2(packf2(xv.z, xv.w), xrv1));
        float2 f0 = unpack2(z0), f1 = unpack2(z1);
        float b0 = fmaxf(f0.x, 0.2f * f0.x);
        float b1 = fmaxf(f0.y, 0.2f * f0.y);
        float b2 = fmaxf(f1.x, 0.2f * f1.x);
        float b3 = fmaxf(f1.y, 0.2f * f1.y);
        float part = b0 * atv[0];
        part = fmaf(b1, atv[1], part);
        part = fmaf(b2, atv[2], part);
        part = fmaf(b3, atv[3], part);
        part += __shfl_xor_sync(0xffffffffu, part, 1);
        part += __shfl_xor_sync(0xffffffffu, part, 2);
        part += __shfl_xor_sync(0xffffffffu, part, 4);
        if (LPH == 16) part += __shfl_xor_sync(0xffffffffu, part, 8);
        float p = ex2(part);
        l += p;
        ull p2 = pack2(p);
        acc0 = fma2(p2, packf2(xv.x, xv.y), acc0);
        acc1 = fma2(p2, packf2(xv.z, xv.w), acc1);
    };

    int i = start;
    for (; i + U <= endi; i += U){
        int2 pr[U];
        #pragma unroll
        for (int e = 0; e < U; e++) pr[e] = __ldg(se + i + e);
        float4 xv[U];
        #pragma unroll
        for (int e = 0; e < U; e++)
            xv[e] = __ldg((const float4*)(xl + (size_t)pr[e].x * CTOT + col0 + lane * 4));

        ull e0[U], e1[U];
        #pragma unroll
        for (int e = 0; e < U; e++){ e0[e] = 0ull; e1[e] = 0ull; }

        #pragma unroll
        for (int kt = 0; kt < 4; kt++){
            float4 aa[U];
            #pragma unroll
            for (int e = 0; e < U; e++)
                aa[e] = __ldg((const float4*)(eattr + (size_t)pr[e].y * 16 + kt * 4));
            #pragma unroll
            for (int k = 0; k < 4; k++){
                ulonglong2 w = *(const ulonglong2*)(wbase + (kt * 4 + k) * 128);
                #pragma unroll
                for (int e = 0; e < U; e++){
                    float av = (k == 0) ? aa[e].x : (k == 1) ? aa[e].y :
                               (k == 2) ? aa[e].z : aa[e].w;
                    ull a2 = pack2(av);
                    e0[e] = fma2(a2, w.x, e0[e]);
                    e1[e] = fma2(a2, w.y, e1[e]);
                }
            }
        }
        #pragma unroll
        for (int e = 0; e < U; e++) FINISH(e0[e], e1[e], xv[e]);
    }

    for (; i < endi; i++){
        int2 pr = __ldg(se + i);
        float4 xv = __ldg((const float4*)(xl + (size_t)pr.x * CTOT + col0 + lane * 4));
        ull e0 = 0ull, e1 = 0ull;
        #pragma unroll
        for (int kt = 0; kt < 4; kt++){
            float4 aa = __ldg((const float4*)(eattr + (size_t)pr.y * 16 + kt * 4));
            #pragma unroll
            for (int k = 0; k < 4; k++){
                ulonglong2 w = *(const ulonglong2*)(wbase + (kt * 4 + k) * 128);
                float av = (k == 0) ? aa.x : (k == 1) ? aa.y : (k == 2) ? aa.z : aa.w;
                ull a2 = pack2(av);
                e0 = fma2(a2, w.x, e0);
                e1 = fma2(a2, w.y, e1);
            }
        }
        FINISH(e0, e1, xv);
    }

    {   // self loop: ee = mean of incoming edge ee (linearity), xl of self
        ull iv = pack2(1.f / (float)max(endi - start, 1));
        ull e0 = fma2(see0, iv, 0ull);
        ull e1 = fma2(see1, iv, 0ull);
        float4 xv = __ldg((const float4*)(xl + (size_t)node * CTOT + col0 + lane * 4));
        FINISH(e0, e1, xv);
    }

    float inv = 1.f / (l + 1e-16f);
    float2 r0 = unpack2(acc0);
    float2 r1 = unpack2(acc1);
    float o0 = r0.x * inv, o1 = r0.y * inv, o2 = r1.x * inv, o3 = r1.y * inv;

    if (!MEAN){
        float4 bo = __ldg((const float4*)(bias + col0 + lane * 4));
        float4 ov;
        ov.x = fmaxf(o0 + bo.x, 0.f);
        ov.y = fmaxf(o1 + bo.y, 0.f);
        ov.z = fmaxf(o2 + bo.z, 0.f);
        ov.w = fmaxf(o3 + bo.w, 0.f);
        *(float4*)(out + (size_t)node * CTOT + col0 + lane * 4) = ov;
    } else {
        o0 += __shfl_xor_sync(0xffffffffu, o0, 16);
        o1 += __shfl_xor_sync(0xffffffffu, o1, 16);
        o2 += __shfl_xor_sync(0xffffffffu, o2, 16);
        o3 += __shfl_xor_sync(0xffffffffu, o3, 16);
        if (lane < 16){
            float* op = out + (size_t)node * 64 + lane * 4;
            atomicAdd(op + 0, 0.25f * o0);
            atomicAdd(op + 1, 0.25f * o1);
            atomicAdd(op + 2, 0.25f * o2);
            atomicAdd(op + 3, 0.25f * o3);
        }
    }
}

// ---------------- global mean pool (applies layer-3 bias + relu) -------------
__device__ __forceinline__ int lowerb(const int* a, int n, int v){
    int lo = 0, hi = n;
    while (lo < hi){ int md = (lo + hi) >> 1; if (a[md] < v) lo = md + 1; else hi = md; }
    return lo;
}

__global__ void pool_k(const float* __restrict__ h3, const int* __restrict__ batch,
                       const float* __restrict__ bof, float* __restrict__ gvec, int n){
    int g = blockIdx.x;
    int lo = lowerb(batch, n, g), hi = lowerb(batch, n, g + 1);
    int t = threadIdx.x;
    int ch = t & 63, rr = t >> 6;
    float b = __ldg(bof + ch);
    float s = 0.f;
    for (int i = lo + rr; i < hi; i += 4)
        s += fmaxf(h3[(size_t)i * 64 + ch] + b, 0.f);
    __shared__ float red[4][64];
    red[rr][ch] = s; __syncthreads();
    if (rr == 0){
        float tot = red[0][ch] + red[1][ch] + red[2][ch] + red[3][ch];
        float c = (float)max(hi - lo, 1);
        gvec[g * 64 + ch] = tot / c;
    }
}

__global__ void final_k(const float* __restrict__ gvec, const float* __restrict__ Wlin,
                        const float* __restrict__ blin, float* __restrict__ out){
    int t = threadIdx.x;
    int g = t >> 4, o = t & 15;
    float s = 0.f;
    #pragma unroll
    for (int k = 0; k < 64; k++) s = fmaf(gvec[g * 64 + k], Wlin[k * 16 + o], s);
    out[t] = s + blin[o];
}

// ---------------- host orchestration (fork-join overlap of prep vs gemm0) ----
extern "C" void kernel_launch(void* const* d_in, const int* in_sizes, int n_in,
                              void* d_out, int out_size){
    const float* x     = (const float*)d_in[0];
    const int*   eidx  = (const int*)  d_in[1];
    const int*   batch = (const int*)  d_in[2];
    const float* eattr = (const float*)d_in[3];
    const float* Wl0 = (const float*)d_in[4],  *bl0 = (const float*)d_in[5];
    const float* Wr0 = (const float*)d_in[6],  *br0 = (const float*)d_in[7];
    const float* We0 = (const float*)d_in[8],  *att0= (const float*)d_in[9];
    const float* bo0 = (const float*)d_in[10];
    const float* Wlh = (const float*)d_in[11], *blh = (const float*)d_in[12];
    const float* Wrh = (const float*)d_in[13], *brh = (const float*)d_in[14];
    const float* Weh = (const float*)d_in[15], *atth= (const float*)d_in[16];
    const float* boh = (const float*)d_in[17];
    const float* Wlf = (const float*)d_in[18], *blf = (const float*)d_in[19];
    const float* Wrf = (const float*)d_in[20], *brf = (const float*)d_in[21];
    const float* Wef = (const float*)d_in[22], *attf= (const float*)d_in[23];
    const float* bof = (const float*)d_in[24];
    const float* Wlin= (const float*)d_in[25], *blin= (const float*)d_in[26];

    int N = in_sizes[0] / 128;
    int E = in_sizes[1] / 2;
    const int* src = eidx;
    const int* dst = eidx + E;

    float *xl, *xr, *h1, *h2, *h3, *gvec;
    int *deg, *rowptr, *cursor;
    int2 *se;
    cudaGetSymbolAddress((void**)&xl,     g_xl);
    cudaGetSymbolAddress((void**)&xr,     g_xr);
    cudaGetSymbolAddress((void**)&h1,     g_h1);
    cudaGetSymbolAddress((void**)&h2,     g_h2);
    cudaGetSymbolAddress((void**)&h3,     g_h3);
    cudaGetSymbolAddress((void**)&gvec,   g_gvec);
    cudaGetSymbolAddress((void**)&deg,    g_deg);
    cudaGetSymbolAddress((void**)&rowptr, g_rowptr);
    cudaGetSymbolAddress((void**)&cursor, g_cursor);
    cudaGetSymbolAddress((void**)&se,     g_se);

    // created once, on the (uncaptured) correctness call
    static cudaStream_t s2 = nullptr;
    static cudaEvent_t evFork = nullptr, evJoin = nullptr;
    if (!s2){
        cudaStreamCreateWithFlags(&s2, cudaStreamNonBlocking);
        cudaEventCreateWithFlags(&evFork, cudaEventDisableTiming);
        cudaEventCreateWithFlags(&evJoin, cudaEventDisableTiming);
    }

    const int GSMEM = (128 * 68 + 2 * 16 * 128) * 4;   // 51200 bytes
    cudaFuncSetAttribute(gemm2<128>, cudaFuncAttributeMaxDynamicSharedMemorySize, GSMEM);
    cudaFuncSetAttribute(gemm2<256>, cudaFuncAttributeMaxDynamicSharedMemorySize, GSMEM);

    dim3 gA(1, (N + 63) / 64, 2), gB(2, (N + 63) / 64, 2);
    dim3 ge1((N + 3) / 4, 1), ge2((N + 3) / 4, 2);

    // fork: prep chain on s2, concurrent with memset + gemm0 on main stream
    cudaEventRecord(evFork, 0);
    cudaStreamWaitEvent(s2, evFork, 0);

    zero_k   <<<(N + 256) / 256, 256, 0, s2>>>(deg, N);
    deg_k    <<<(E + 255) / 256, 256, 0, s2>>>(dst, deg, E);
    scan_k   <<<1, 1024, 0, s2>>>(deg, rowptr, cursor, N);
    scatter_k<<<(E + 255) / 256, 256, 0, s2>>>(src, dst, cursor, se, E);
    cudaEventRecord(evJoin, s2);

    cudaMemsetAsync(h3, 0, (size_t)N * 64 * sizeof(float));
    gemm2<128><<<gA, 128, GSMEM>>>(x, Wl0, bl0, Wr0, br0, xl, xr, N);

    // join: edge pass needs rowptr/se from s2
    cudaStreamWaitEvent(0, evJoin, 0);

    gat_edge<128, 8, false><<<ge1, 128>>>(xl, xr, We0, att0, bo0, eattr,
                                          rowptr, se, h1, N);
    gemm2<128><<<gA, 128, GSMEM>>>(h1, Wlh, blh, Wrh, brh, xl, xr, N);
    gat_edge<128, 8, false><<<ge1, 128>>>(xl, xr, Weh, atth, boh, eattr,
                                          rowptr, se, h2, N);
    gemm2<256><<<gB, 128, GSMEM>>>(h2, Wlf, blf, Wrf, brf, xl, xr, N);
    gat_edge<256, 16, true><<<ge2, 128>>>(xl, xr, Wef, attf, bof, eattr,
                                          rowptr, se, h3, N);
    pool_k <<<64, 256>>>(h3, batch, bof, gvec, N);
    final_k<<<1, 1024>>>(gvec, Wlin, blin, (float*)d_out);
}